// round 9
// baseline (speedup 1.0000x reference)
#include <cuda_runtime.h>
#include <cuda_bf16.h>
#include <math_constants.h>
#include <cstdint>

// GatingNetwork: out = softmax(mask_topk(x @ W^T + b, k=8), axis=-1)
// x: [N=16384, D=4096] f32, W: [E=128, D] f32, b: [E] f32, k=8. out: [N, E] f32.
//
// Round 8: R7 (mma.sync tf32 3-term + two-level accumulation) was DRAM-bound
// at 834 GB/s (dur == bytes/BW exactly). This round: 4-stage cp.async pipeline
// (~144KB/SM in flight) so x streams at full rate and the tensor pipe becomes
// the limiter (~170us tensor-active). Copy-issue moved after the barrier to
// keep stage reuse race-free at depth 3.

#define NTHREADS 256
#define BM 128
#define BN 128
#define BK 32
#define LSTRIDE 132
#define ASTRIDE 36              // floats per A row in smem (conflict-free frags)

#define NSTAGES 4
#define A_BYTES 18432           // 128 rows * 144 B
#define B_BYTES 32768           // 16KB hi + 16KB lo, fragment-ordered
#define STAGE_BYTES (A_BYTES + B_BYTES)          // 51200
#define SMEM_BYTES (NSTAGES * STAGE_BYTES)       // 204800

// Pre-split, fragment-ordered W: per iter 32KB (16KB hi + 16KB lo)
__device__ __align__(16) unsigned char g_Wfrag[128 * 32768];

__device__ __forceinline__ float to_tf32(float v) {
    float r;
    asm("cvt.rna.tf32.f32 %0, %1;" : "=f"(r) : "f"(v));
    return r;
}
__device__ __forceinline__ uint32_t smem_u32(const void* p) {
    uint32_t a;
    asm("{ .reg .u64 t; cvta.to.shared.u64 t, %1; cvt.u32.u64 %0, t; }"
        : "=r"(a) : "l"(p));
    return a;
}

#define CP_ASYNC16(dst, src) \
    asm volatile("cp.async.cg.shared.global [%0], [%1], 16;" \
                 :: "r"(dst), "l"(src) : "memory")
#define CP_COMMIT() asm volatile("cp.async.commit_group;" ::: "memory")
#define CP_WAIT(n)  asm volatile("cp.async.wait_group %0;" :: "n"(n) : "memory")

#define MMA_TF32(c, a, b) \
    asm volatile("mma.sync.aligned.m16n8k8.row.col.f32.tf32.tf32.f32 " \
        "{%0,%1,%2,%3}, {%4,%5,%6,%7}, {%8,%9}, {%0,%1,%2,%3};" \
        : "+f"((c)[0]), "+f"((c)[1]), "+f"((c)[2]), "+f"((c)[3]) \
        : "r"((a)[0]), "r"((a)[1]), "r"((a)[2]), "r"((a)[3]), \
          "r"((b)[0]), "r"((b)[1]))

__device__ __forceinline__ float warpReduceMax(float v) {
    #pragma unroll
    for (int off = 16; off > 0; off >>= 1)
        v = fmaxf(v, __shfl_xor_sync(0xffffffffu, v, off));
    return v;
}
__device__ __forceinline__ float warpReduceSum(float v) {
    #pragma unroll
    for (int off = 16; off > 0; off >>= 1)
        v += __shfl_xor_sync(0xffffffffu, v, off);
    return v;
}

// ---------------- prep: split W to tf32 hi/lo in B-fragment order ----------------
__global__ void prep_w_kernel(const float* __restrict__ W, int n4, int D) {
    int i = blockIdx.x * blockDim.x + threadIdx.x;
    if (i >= n4) return;
    int d4PerRow = D / 4;
    int e  = i / d4PerRow;
    int d0 = (i - e * d4PerRow) * 4;
    float4 v = reinterpret_cast<const float4*>(W)[i];
    float4 h, l;
    h.x = to_tf32(v.x); l.x = to_tf32(v.x - h.x);
    h.y = to_tf32(v.y); l.y = to_tf32(v.y - h.y);
    h.z = to_tf32(v.z); l.z = to_tf32(v.z - h.z);
    h.w = to_tf32(v.w); l.w = to_tf32(v.w - h.w);
    int it = d0 >> 5;
    int kk = d0 & 31;
    int ks = kk >> 3;
    int chalf = (kk & 7) >> 2;
    int nt = e >> 3;
    int lane0 = (e & 7) * 4;
    size_t base = (size_t)it * 32768;
    unsigned char* pH = g_Wfrag + base;
    unsigned char* pL = g_Wfrag + base + 16384;
    int o = ((ks * 16 + nt) * 32 + lane0) * 8 + chalf * 4;
    *reinterpret_cast<float*>(pH + o)      = h.x;
    *reinterpret_cast<float*>(pH + o + 8)  = h.y;
    *reinterpret_cast<float*>(pH + o + 16) = h.z;
    *reinterpret_cast<float*>(pH + o + 24) = h.w;
    *reinterpret_cast<float*>(pL + o)      = l.x;
    *reinterpret_cast<float*>(pL + o + 8)  = l.y;
    *reinterpret_cast<float*>(pL + o + 16) = l.z;
    *reinterpret_cast<float*>(pL + o + 24) = l.w;
}

// ---------------- main fused kernel ----------------
__global__ __launch_bounds__(NTHREADS, 1)
void gating_mma_kernel(const float* __restrict__ x,
                       const float* __restrict__ bias,
                       const int* __restrict__ kptr,
                       float* __restrict__ out,
                       int N, int D, int E) {
    extern __shared__ char smem[];
    const uint32_t sb = smem_u32(smem);
    const int tid = threadIdx.x;
    const int lane = tid & 31;
    const int wid = tid >> 5;
    const int warpM = wid & 1;      // 0..1  (64 rows each)
    const int warpN = wid >> 1;     // 0..3  (32 cols each)
    const int m0 = blockIdx.x * BM;

    float accT[4][4][4];
    float accC[4][4][4];
    #pragma unroll
    for (int mt = 0; mt < 4; mt++)
        #pragma unroll
        for (int nt = 0; nt < 4; nt++)
            #pragma unroll
            for (int q = 0; q < 4; q++) { accT[mt][nt][q] = 0.0f; accC[mt][nt][q] = 0.0f; }

    const int iters = D / BK;       // 128

    // per-thread copy slots (constant): A: f = tid+u*256, row=f>>3, c4=f&7
    // A smem addr = row*144 + c4*16; B: 2048 16B chunks linear.

    // ---- prologue: fill stages 0..NSTAGES-2 ----
    #pragma unroll
    for (int s = 0; s < NSTAGES - 1; s++) {
        const uint32_t aBase = sb + (uint32_t)s * STAGE_BYTES;
        const uint32_t bBase = aBase + A_BYTES;
        const int k0 = s * BK;
        #pragma unroll
        for (int u = 0; u < 4; u++) {
            int f = tid + u * NTHREADS;
            int row = f >> 3, c4 = f & 7;
            CP_ASYNC16(aBase + (uint32_t)(row * 144 + c4 * 16),
                       &x[(size_t)(m0 + row) * D + k0 + c4 * 4]);
        }
        const unsigned char* wsrc = g_Wfrag + (size_t)s * 32768;
        #pragma unroll
        for (int u = 0; u < 8; u++) {
            int idx = tid + u * NTHREADS;
            CP_ASYNC16(bBase + (uint32_t)(idx * 16), wsrc + (size_t)idx * 16);
        }
        CP_COMMIT();
    }

    for (int it = 0; it < iters; it++) {
        const int stage = it & (NSTAGES - 1);

        // ---- wait for stage `it`, then barrier (also fences stage reuse) ----
        if (it < iters - 2)       CP_WAIT(2);
        else if (it == iters - 2) CP_WAIT(1);
        else                      CP_WAIT(0);
        __syncthreads();

        // ---- issue stage it+NSTAGES-1 (safe: all warps done with it-1) ----
        if (it + NSTAGES - 1 < iters) {
            const int is = it + NSTAGES - 1;
            const uint32_t aBase = sb + (uint32_t)(is & (NSTAGES - 1)) * STAGE_BYTES;
            const uint32_t bBase = aBase + A_BYTES;
            const int k0 = is * BK;
            #pragma unroll
            for (int u = 0; u < 4; u++) {
                int f = tid + u * NTHREADS;
                int row = f >> 3, c4 = f & 7;
                CP_ASYNC16(aBase + (uint32_t)(row * 144 + c4 * 16),
                           &x[(size_t)(m0 + row) * D + k0 + c4 * 4]);
            }
            const unsigned char* wsrc = g_Wfrag + (size_t)is * 32768;
            #pragma unroll
            for (int u = 0; u < 8; u++) {
                int idx = tid + u * NTHREADS;
                CP_ASYNC16(bBase + (uint32_t)(idx * 16), wsrc + (size_t)idx * 16);
            }
            CP_COMMIT();
        }

        // ---- mma phase: A raw -> on-the-fly tf32 hi/lo split ----
        const float* aRaw = reinterpret_cast<const float*>(
            smem + (size_t)stage * STAGE_BYTES);
        const char* bB = smem + (size_t)stage * STAGE_BYTES + A_BYTES;

        #pragma unroll
        for (int ks = 0; ks < 4; ks++) {
            uint32_t bh[4][2], bl[4][2];
            #pragma unroll
            for (int nt = 0; nt < 4; nt++) {
                int ob = ((ks * 16 + warpN * 4 + nt) * 32 + lane) * 8;
                uint2 vh = *reinterpret_cast<const uint2*>(bB + ob);
                uint2 vl = *reinterpret_cast<const uint2*>(bB + 16384 + ob);
                bh[nt][0] = vh.x; bh[nt][1] = vh.y;
                bl[nt][0] = vl.x; bl[nt][1] = vl.y;
            }
            #pragma unroll
            for (int mt = 0; mt < 4; mt++) {
                int r = (warpM * 4 + mt) * 16 + (lane >> 2);
                int i0 = r * ASTRIDE + ks * 8 + (lane & 3);
                float r0 = aRaw[i0];
                float r1 = aRaw[i0 + 8 * ASTRIDE];
                float r2 = aRaw[i0 + 4];
                float r3 = aRaw[i0 + 8 * ASTRIDE + 4];
                uint32_t ah[4], al[4];
                float h;
                h = to_tf32(r0); ah[0] = __float_as_uint(h); al[0] = __float_as_uint(to_tf32(r0 - h));
                h = to_tf32(r1); ah[1] = __float_as_uint(h); al[1] = __float_as_uint(to_tf32(r1 - h));
                h = to_tf32(r2); ah[2] = __float_as_uint(h); al[2] = __float_as_uint(to_tf32(r2 - h));
                h = to_tf32(r3); ah[3] = __float_as_uint(h); al[3] = __float_as_uint(to_tf32(r3 - h));
                #pragma unroll
                for (int nt = 0; nt < 4; nt++) {
                    MMA_TF32(accC[mt][nt], ah, bh[nt]);
                    MMA_TF32(accC[mt][nt], ah, bl[nt]);
                    MMA_TF32(accC[mt][nt], al, bh[nt]);
                }
            }
        }

        // ---- two-level fold every 4 iters (128 K-terms per chunk) ----
        if ((it & 3) == 3) {
            #pragma unroll
            for (int mt = 0; mt < 4; mt++)
                #pragma unroll
                for (int nt = 0; nt < 4; nt++)
                    #pragma unroll
                    for (int q = 0; q < 4; q++) {
                        accT[mt][nt][q] += accC[mt][nt][q];
                        accC[mt][nt][q] = 0.0f;
                    }
        }
    }
    __syncthreads();   // all warps done with last stage before logits overlay

    // ---- epilogue: fragments -> smem logits ----
    float* logits = reinterpret_cast<float*>(smem);
    #pragma unroll
    for (int mt = 0; mt < 4; mt++)
        #pragma unroll
        for (int nt = 0; nt < 4; nt++) {
            int r0 = warpM * 64 + mt * 16 + (lane >> 2);
            int c0 = warpN * 32 + nt * 8 + (lane & 3) * 2;
            logits[r0 * LSTRIDE + c0]           = accT[mt][nt][0];
            logits[r0 * LSTRIDE + c0 + 1]       = accT[mt][nt][1];
            logits[(r0 + 8) * LSTRIDE + c0]     = accT[mt][nt][2];
            logits[(r0 + 8) * LSTRIDE + c0 + 1] = accT[mt][nt][3];
        }
    __syncthreads();

    // ---- per-row top-k threshold + masked softmax (proven R3 epilogue) ----
    const int k = kptr[0];
    float4 bb4 = *reinterpret_cast<const float4*>(&bias[lane * 4]);

    for (int r = wid; r < BM; r += NTHREADS / 32) {
        float4 vv = *reinterpret_cast<const float4*>(&logits[r * LSTRIDE + lane * 4]);
        float vals[4] = {vv.x + bb4.x, vv.y + bb4.y, vv.z + bb4.z, vv.w + bb4.w};
        bool removed[4] = {false, false, false, false};

        float rowMax = -CUDART_INF_F;
        float thr = -CUDART_INF_F;
        for (int itk = 0; itk < k; itk++) {
            float localMax = -CUDART_INF_F;
            #pragma unroll
            for (int j = 0; j < 4; j++)
                if (!removed[j]) localMax = fmaxf(localMax, vals[j]);
            float wmax = warpReduceMax(localMax);
            if (itk == 0) rowMax = wmax;
            thr = wmax;
            unsigned ball = __ballot_sync(0xffffffffu, localMax == wmax);
            int src = __ffs(ball) - 1;
            if (lane == src) {
                #pragma unroll
                for (int j = 0; j < 4; j++) {
                    if (!removed[j] && vals[j] == wmax) { removed[j] = true; break; }
                }
            }
        }

        float ex[4];
        float s = 0.0f;
        #pragma unroll
        for (int j = 0; j < 4; j++) {
            ex[j] = (vals[j] >= thr) ? expf(vals[j] - rowMax) : 0.0f;
            s += ex[j];
        }
        s = warpReduceSum(s);
        float inv = 1.0f / s;
        float4 o = make_float4(ex[0] * inv, ex[1] * inv, ex[2] * inv, ex[3] * inv);
        *reinterpret_cast<float4*>(&out[(size_t)(m0 + r) * E + lane * 4]) = o;
    }
}

extern "C" void kernel_launch(void* const* d_in, const int* in_sizes, int n_in,
                              void* d_out, int out_size) {
    const float* x  = (const float*)d_in[0];
    const float* W  = (const float*)d_in[1];
    const float* b  = (const float*)d_in[2];
    const int*   kp = (const int*)d_in[3];

    int E = in_sizes[2];                 // 128
    int D = in_sizes[1] / E;             // 4096
    int N = in_sizes[0] / D;             // 16384
    float* out = (float*)d_out;

    static bool attrSet = false;
    if (!attrSet) {
        cudaFuncSetAttribute(gating_mma_kernel,
                             cudaFuncAttributeMaxDynamicSharedMemorySize, SMEM_BYTES);
        attrSet = true;
    }

    int n4 = (E * D) / 4;
    prep_w_kernel<<<(n4 + 255) / 256, 256>>>(W, n4, D);

    dim3 grid(N / BM);
    gating_mma_kernel<<<grid, NTHREADS, SMEM_BYTES>>>(x, b, kp, out, N, D, E);
}

// round 11
// speedup vs baseline: 1.0146x; 1.0146x over previous
#include <cuda_runtime.h>
#include <cuda_bf16.h>
#include <math_constants.h>
#include <cstdint>

// GatingNetwork: out = softmax(mask_topk(x @ W^T + b, k=8), axis=-1)
// x: [N=16384, D=4096] f32, W: [E=128, D] f32, b: [E] f32, k=8. out: [N, E] f32.
//
// Round 10: resubmit of R9 (infra failure, no kernel verdict). 512 threads
// (16 warps, 32x32 per-warp tile) for 4 warps/SMSP latency hiding + term-major
// MMA ordering (dependent-chain distance 1 -> 4). 3xTF32 decomposition with
// two-level accumulation, 4-stage cp.async pipeline, proven top-k/softmax.

#define NTHREADS 512
#define BM 128
#define BN 128
#define BK 32
#define LSTRIDE 132
#define ASTRIDE 36              // floats per A row in smem (conflict-free frags)

#define NSTAGES 4
#define A_BYTES 18432           // 128 rows * 144 B
#define B_BYTES 32768           // 16KB hi + 16KB lo, fragment-ordered
#define STAGE_BYTES (A_BYTES + B_BYTES)          // 51200
#define SMEM_BYTES (NSTAGES * STAGE_BYTES)       // 204800

// Pre-split, fragment-ordered W: per iter 32KB (16KB hi + 16KB lo)
__device__ __align__(16) unsigned char g_Wfrag[128 * 32768];

__device__ __forceinline__ float to_tf32(float v) {
    float r;
    asm("cvt.rna.tf32.f32 %0, %1;" : "=f"(r) : "f"(v));
    return r;
}
__device__ __forceinline__ uint32_t smem_u32(const void* p) {
    uint32_t a;
    asm("{ .reg .u64 t; cvta.to.shared.u64 t, %1; cvt.u32.u64 %0, t; }"
        : "=r"(a) : "l"(p));
    return a;
}

#define CP_ASYNC16(dst, src) \
    asm volatile("cp.async.cg.shared.global [%0], [%1], 16;" \
                 :: "r"(dst), "l"(src) : "memory")
#define CP_COMMIT() asm volatile("cp.async.commit_group;" ::: "memory")
#define CP_WAIT(n)  asm volatile("cp.async.wait_group %0;" :: "n"(n) : "memory")

#define MMA_TF32(c, a, b) \
    asm volatile("mma.sync.aligned.m16n8k8.row.col.f32.tf32.tf32.f32 " \
        "{%0,%1,%2,%3}, {%4,%5,%6,%7}, {%8,%9}, {%0,%1,%2,%3};" \
        : "+f"((c)[0]), "+f"((c)[1]), "+f"((c)[2]), "+f"((c)[3]) \
        : "r"((a)[0]), "r"((a)[1]), "r"((a)[2]), "r"((a)[3]), \
          "r"((b)[0]), "r"((b)[1]))

__device__ __forceinline__ float warpReduceMax(float v) {
    #pragma unroll
    for (int off = 16; off > 0; off >>= 1)
        v = fmaxf(v, __shfl_xor_sync(0xffffffffu, v, off));
    return v;
}
__device__ __forceinline__ float warpReduceSum(float v) {
    #pragma unroll
    for (int off = 16; off > 0; off >>= 1)
        v += __shfl_xor_sync(0xffffffffu, v, off);
    return v;
}

// ---------------- prep: split W to tf32 hi/lo in B-fragment order ----------------
__global__ void prep_w_kernel(const float* __restrict__ W, int n4, int D) {
    int i = blockIdx.x * blockDim.x + threadIdx.x;
    if (i >= n4) return;
    int d4PerRow = D / 4;
    int e  = i / d4PerRow;
    int d0 = (i - e * d4PerRow) * 4;
    float4 v = reinterpret_cast<const float4*>(W)[i];
    float4 h, l;
    h.x = to_tf32(v.x); l.x = to_tf32(v.x - h.x);
    h.y = to_tf32(v.y); l.y = to_tf32(v.y - h.y);
    h.z = to_tf32(v.z); l.z = to_tf32(v.z - h.z);
    h.w = to_tf32(v.w); l.w = to_tf32(v.w - h.w);
    int it = d0 >> 5;
    int kk = d0 & 31;
    int ks = kk >> 3;
    int chalf = (kk & 7) >> 2;
    int nt = e >> 3;
    int lane0 = (e & 7) * 4;
    size_t base = (size_t)it * 32768;
    unsigned char* pH = g_Wfrag + base;
    unsigned char* pL = g_Wfrag + base + 16384;
    int o = ((ks * 16 + nt) * 32 + lane0) * 8 + chalf * 4;
    *reinterpret_cast<float*>(pH + o)      = h.x;
    *reinterpret_cast<float*>(pH + o + 8)  = h.y;
    *reinterpret_cast<float*>(pH + o + 16) = h.z;
    *reinterpret_cast<float*>(pH + o + 24) = h.w;
    *reinterpret_cast<float*>(pL + o)      = l.x;
    *reinterpret_cast<float*>(pL + o + 8)  = l.y;
    *reinterpret_cast<float*>(pL + o + 16) = l.z;
    *reinterpret_cast<float*>(pL + o + 24) = l.w;
}

// ---------------- main fused kernel ----------------
__global__ __launch_bounds__(NTHREADS, 1)
void gating_mma_kernel(const float* __restrict__ x,
                       const float* __restrict__ bias,
                       const int* __restrict__ kptr,
                       float* __restrict__ out,
                       int N, int D, int E) {
    extern __shared__ char smem[];
    const uint32_t sb = smem_u32(smem);
    const int tid = threadIdx.x;
    const int lane = tid & 31;
    const int wid = tid >> 5;         // 0..15
    const int warpM = wid & 3;        // 0..3  (32 rows each)
    const int warpN = wid >> 2;       // 0..3  (32 cols each)
    const int m0 = blockIdx.x * BM;

    float accT[2][4][4];
    float accC[2][4][4];
    #pragma unroll
    for (int mt = 0; mt < 2; mt++)
        #pragma unroll
        for (int nt = 0; nt < 4; nt++)
            #pragma unroll
            for (int q = 0; q < 4; q++) { accT[mt][nt][q] = 0.0f; accC[mt][nt][q] = 0.0f; }

    const int iters = D / BK;       // 128

    // copy slots: A has 1024 16B slots (f = tid + u*512, u<2): row=f>>3, c4=f&7
    //             B has 2048 16B chunks (idx = tid + u*512, u<4), linear

    // ---- prologue: fill stages 0..NSTAGES-2 ----
    #pragma unroll
    for (int s = 0; s < NSTAGES - 1; s++) {
        const uint32_t aBase = sb + (uint32_t)s * STAGE_BYTES;
        const uint32_t bBase = aBase + A_BYTES;
        const int k0 = s * BK;
        #pragma unroll
        for (int u = 0; u < 2; u++) {
            int f = tid + u * NTHREADS;
            int row = f >> 3, c4 = f & 7;
            CP_ASYNC16(aBase + (uint32_t)(row * 144 + c4 * 16),
                       &x[(size_t)(m0 + row) * D + k0 + c4 * 4]);
        }
        const unsigned char* wsrc = g_Wfrag + (size_t)s * 32768;
        #pragma unroll
        for (int u = 0; u < 4; u++) {
            int idx = tid + u * NTHREADS;
            CP_ASYNC16(bBase + (uint32_t)(idx * 16), wsrc + (size_t)idx * 16);
        }
        CP_COMMIT();
    }

    for (int it = 0; it < iters; it++) {
        const int stage = it & (NSTAGES - 1);

        if (it < iters - 2)       CP_WAIT(2);
        else if (it == iters - 2) CP_WAIT(1);
        else                      CP_WAIT(0);
        __syncthreads();

        // ---- issue stage it+NSTAGES-1 (safe after barrier) ----
        if (it + NSTAGES - 1 < iters) {
            const int is = it + NSTAGES - 1;
            const uint32_t aBase = sb + (uint32_t)(is & (NSTAGES - 1)) * STAGE_BYTES;
            const uint32_t bBase = aBase + A_BYTES;
            const int k0 = is * BK;
            #pragma unroll
            for (int u = 0; u < 2; u++) {
                int f = tid + u * NTHREADS;
                int row = f >> 3, c4 = f & 7;
                CP_ASYNC16(aBase + (uint32_t)(row * 144 + c4 * 16),
                           &x[(size_t)(m0 + row) * D + k0 + c4 * 4]);
            }
            const unsigned char* wsrc = g_Wfrag + (size_t)is * 32768;
            #pragma unroll
            for (int u = 0; u < 4; u++) {
                int idx = tid + u * NTHREADS;
                CP_ASYNC16(bBase + (uint32_t)(idx * 16), wsrc + (size_t)idx * 16);
            }
            CP_COMMIT();
        }

        // ---- mma phase: A raw -> tf32 hi/lo split; term-major issue order ----
        const float* aRaw = reinterpret_cast<const float*>(
            smem + (size_t)stage * STAGE_BYTES);
        const char* bB = smem + (size_t)stage * STAGE_BYTES + A_BYTES;

        #pragma unroll
        for (int ks = 0; ks < 4; ks++) {
            uint32_t bh[4][2], bl[4][2];
            #pragma unroll
            for (int nt = 0; nt < 4; nt++) {
                int ob = ((ks * 16 + warpN * 4 + nt) * 32 + lane) * 8;
                uint2 vh = *reinterpret_cast<const uint2*>(bB + ob);
                uint2 vl = *reinterpret_cast<const uint2*>(bB + 16384 + ob);
                bh[nt][0] = vh.x; bh[nt][1] = vh.y;
                bl[nt][0] = vl.x; bl[nt][1] = vl.y;
            }
            #pragma unroll
            for (int mt = 0; mt < 2; mt++) {
                int r = (warpM * 2 + mt) * 16 + (lane >> 2);
                int i0 = r * ASTRIDE + ks * 8 + (lane & 3);
                float r0 = aRaw[i0];
                float r1 = aRaw[i0 + 8 * ASTRIDE];
                float r2 = aRaw[i0 + 4];
                float r3 = aRaw[i0 + 8 * ASTRIDE + 4];
                uint32_t ah[4], al[4];
                float h;
                h = to_tf32(r0); ah[0] = __float_as_uint(h); al[0] = __float_as_uint(to_tf32(r0 - h));
                h = to_tf32(r1); ah[1] = __float_as_uint(h); al[1] = __float_as_uint(to_tf32(r1 - h));
                h = to_tf32(r2); ah[2] = __float_as_uint(h); al[2] = __float_as_uint(to_tf32(r2 - h));
                h = to_tf32(r3); ah[3] = __float_as_uint(h); al[3] = __float_as_uint(to_tf32(r3 - h));
                // term-major: chain distance 4 between same-acc MMAs
                #pragma unroll
                for (int nt = 0; nt < 4; nt++) MMA_TF32(accC[mt][nt], ah, bh[nt]);
                #pragma unroll
                for (int nt = 0; nt < 4; nt++) MMA_TF32(accC[mt][nt], ah, bl[nt]);
                #pragma unroll
                for (int nt = 0; nt < 4; nt++) MMA_TF32(accC[mt][nt], al, bh[nt]);
            }
        }

        // ---- two-level fold every 4 iters (128 K-terms per chunk) ----
        if ((it & 3) == 3) {
            #pragma unroll
            for (int mt = 0; mt < 2; mt++)
                #pragma unroll
                for (int nt = 0; nt < 4; nt++)
                    #pragma unroll
                    for (int q = 0; q < 4; q++) {
                        accT[mt][nt][q] += accC[mt][nt][q];
                        accC[mt][nt][q] = 0.0f;
                    }
        }
    }
    __syncthreads();   // all warps done with last stage before logits overlay

    // ---- epilogue: fragments -> smem logits ----
    float* logits = reinterpret_cast<float*>(smem);
    #pragma unroll
    for (int mt = 0; mt < 2; mt++)
        #pragma unroll
        for (int nt = 0; nt < 4; nt++) {
            int r0 = warpM * 32 + mt * 16 + (lane >> 2);
            int c0 = warpN * 32 + nt * 8 + (lane & 3) * 2;
            logits[r0 * LSTRIDE + c0]           = accT[mt][nt][0];
            logits[r0 * LSTRIDE + c0 + 1]       = accT[mt][nt][1];
            logits[(r0 + 8) * LSTRIDE + c0]     = accT[mt][nt][2];
            logits[(r0 + 8) * LSTRIDE + c0 + 1] = accT[mt][nt][3];
        }
    __syncthreads();

    // ---- per-row top-k threshold + masked softmax (proven R3 epilogue) ----
    const int k = kptr[0];
    float4 bb4 = *reinterpret_cast<const float4*>(&bias[lane * 4]);

    for (int r = wid; r < BM; r += NTHREADS / 32) {
        float4 vv = *reinterpret_cast<const float4*>(&logits[r * LSTRIDE + lane * 4]);
        float vals[4] = {vv.x + bb4.x, vv.y + bb4.y, vv.z + bb4.z, vv.w + bb4.w};
        bool removed[4] = {false, false, false, false};

        float rowMax = -CUDART_INF_F;
        float thr = -CUDART_INF_F;
        for (int itk = 0; itk < k; itk++) {
            float localMax = -CUDART_INF_F;
            #pragma unroll
            for (int j = 0; j < 4; j++)
                if (!removed[j]) localMax = fmaxf(localMax, vals[j]);
            float wmax = warpReduceMax(localMax);
            if (itk == 0) rowMax = wmax;
            thr = wmax;
            unsigned ball = __ballot_sync(0xffffffffu, localMax == wmax);
            int src = __ffs(ball) - 1;
            if (lane == src) {
                #pragma unroll
                for (int j = 0; j < 4; j++) {
                    if (!removed[j] && vals[j] == wmax) { removed[j] = true; break; }
                }
            }
        }

        float ex[4];
        float s = 0.0f;
        #pragma unroll
        for (int j = 0; j < 4; j++) {
            ex[j] = (vals[j] >= thr) ? expf(vals[j] - rowMax) : 0.0f;
            s += ex[j];
        }
        s = warpReduceSum(s);
        float inv = 1.0f / s;
        float4 o = make_float4(ex[0] * inv, ex[1] * inv, ex[2] * inv, ex[3] * inv);
        *reinterpret_cast<float4*>(&out[(size_t)(m0 + r) * E + lane * 4]) = o;
    }
}

extern "C" void kernel_launch(void* const* d_in, const int* in_sizes, int n_in,
                              void* d_out, int out_size) {
    const float* x  = (const float*)d_in[0];
    const float* W  = (const float*)d_in[1];
    const float* b  = (const float*)d_in[2];
    const int*   kp = (const int*)d_in[3];

    int E = in_sizes[2];                 // 128
    int D = in_sizes[1] / E;             // 4096
    int N = in_sizes[0] / D;             // 16384
    float* out = (float*)d_out;

    static bool attrSet = false;
    if (!attrSet) {
        cudaFuncSetAttribute(gating_mma_kernel,
                             cudaFuncAttributeMaxDynamicSharedMemorySize, SMEM_BYTES);
        attrSet = true;
    }

    int n4 = (E * D) / 4;
    prep_w_kernel<<<(n4 + 255) / 256, 256>>>(W, n4, D);

    dim3 grid(N / BM);
    gating_mma_kernel<<<grid, NTHREADS, SMEM_BYTES>>>(x, b, kp, out, N, D, E);
}